// round 13
// baseline (speedup 1.0000x reference)
#include <cuda_runtime.h>
#include <cuda_fp16.h>
#include <cstdint>

// Problem constants
#define BB 4096
#define TT 32
#define CC 384
#define HH 6
#define DH 64
#define LL 6
#define VV 80
#define NT (BB*TT)          // 131072 tokens
#define C4 (4*CC)           // 1536
#define QKVN (3*CC)         // 1152

// ---------------------------------------------------------------------------
// Scratch (static device globals; no runtime allocation allowed)
// ---------------------------------------------------------------------------
__device__ float  g_x   [(size_t)NT * CC];      // residual stream (fp32)
__device__ float  g_qkv [(size_t)NT * QKVN];    // q|k|v (fp32, attention input)
__device__ float  g_hf  [(size_t)NT * CC];      // final LN output (fp32)
__device__ __half g_ha  [(size_t)NT * CC];      // layer LN output (half, GEMM A)
__device__ __half g_o   [(size_t)NT * CC];      // attention output (half)
__device__ __half g_hid [(size_t)NT * C4];      // MLP hidden (half)
// Transposed (K-major, [N][K]) half weights
__device__ __half g_wqkvT[(size_t)LL * QKVN * CC];
__device__ __half g_woT  [(size_t)LL * CC * CC];
__device__ __half g_w1T  [(size_t)LL * C4 * CC];
__device__ __half g_w2T  [(size_t)LL * CC * C4];

// ---------------------------------------------------------------------------
// PTX helpers (sm_80+ baseline — no 'a'-variant instructions)
// ---------------------------------------------------------------------------
__device__ __forceinline__ uint32_t smem_u32(const void* p) {
    return (uint32_t)__cvta_generic_to_shared(p);
}
__device__ __forceinline__ void cp_async16(uint32_t s, const void* g) {
    asm volatile("cp.async.cg.shared.global [%0], [%1], 16;" :: "r"(s), "l"(g));
}
__device__ __forceinline__ void cp_commit() {
    asm volatile("cp.async.commit_group;" ::: "memory");
}
template<int N> __device__ __forceinline__ void cp_wait() {
    asm volatile("cp.async.wait_group %0;" :: "n"(N) : "memory");
}
__device__ __forceinline__ void ldmat_x4(uint32_t* r, uint32_t addr) {
    asm volatile("ldmatrix.sync.aligned.m8n8.x4.shared.b16 {%0,%1,%2,%3}, [%4];"
                 : "=r"(r[0]), "=r"(r[1]), "=r"(r[2]), "=r"(r[3]) : "r"(addr));
}
__device__ __forceinline__ void mma_f16(float* d, const uint32_t* a, uint32_t b0, uint32_t b1) {
    asm volatile(
        "mma.sync.aligned.m16n8k16.row.col.f32.f16.f16.f32 "
        "{%0,%1,%2,%3}, {%4,%5,%6,%7}, {%8,%9}, {%0,%1,%2,%3};"
        : "+f"(d[0]), "+f"(d[1]), "+f"(d[2]), "+f"(d[3])
        : "r"(a[0]), "r"(a[1]), "r"(a[2]), "r"(a[3]), "r"(b0), "r"(b1));
}

// ---------------------------------------------------------------------------
// fp16 ldmatrix GEMM: CTA 128x128, BK=64, 3-stage cp.async.
// 512 threads / 16 warps (4x4 grid), warp tile 32x32: 4 resident warps per
// SMSP for latency hiding, ~90 regs/thread (no cap, no spills).
// ---------------------------------------------------------------------------
#define A_SZ 16384                 // 128 rows * 128B
#define STAGE_BYTES 32768          // A + B
#define NSTG 3
#define DYN_SMEM (NSTG*STAGE_BYTES)  // 98304

#define ISSUE_STAGE(buf, ch) do {                                            \
    uint32_t bA_ = sb + (uint32_t)(buf) * STAGE_BYTES + offA0;               \
    uint32_t bB_ = bA_ + A_SZ;                                               \
    const __half* pa_ = pA0 + (size_t)(ch) * 64;                             \
    const __half* pb_ = pB0 + (size_t)(ch) * 64;                             \
    _Pragma("unroll")                                                        \
    for (int i_ = 0; i_ < 2; i_++) {                                         \
        cp_async16(bA_ + (uint32_t)(i_ * 8192), pa_);                        \
        cp_async16(bB_ + (uint32_t)(i_ * 8192), pb_);                        \
        pa_ += kstep; pb_ += kstep;                                          \
    }                                                                        \
} while (0)

template<bool BIAS, bool RELU, bool RESID, bool OUTH>
__global__ __launch_bounds__(512)
void mma_gemm(const __half* __restrict__ A, const __half* __restrict__ Bt,
              const float* __restrict__ bias, const float* __restrict__ resid,
              void* __restrict__ CoutV, int N, int K)
{
    extern __shared__ char smem[];
    const uint32_t sb = smem_u32(smem);
    const int tid = threadIdx.x;
    const int wid = tid >> 5, lid = tid & 31;
    const int m0 = blockIdx.y * 128;
    const int n0 = blockIdx.x * 128;
    const int wm = (wid & 3) * 32;     // warp M offset (4 warps over M)
    const int wn = (wid >> 2) * 32;    // warp N offset (4 warps over N)
    const int g  = lid >> 2;           // groupID
    const int t  = lid & 3;            // thread-in-group

    // cp.async mapping: thread covers rows (tid>>3) and +64; 16B chunk col tid&7.
    const int row0 = tid >> 3;         // 0..63
    const int ccol = tid & 7;
    const uint32_t offA0 = (uint32_t)(row0 * 128 + ((ccol ^ (row0 & 7)) << 4));
    const __half* pA0 = A  + (size_t)(m0 + row0) * K + ccol * 8;
    const __half* pB0 = Bt + (size_t)(n0 + row0) * K + ccol * 8;
    const size_t kstep = (size_t)64 * K;

    // ldmatrix per-lane addressing
    const int lrow = lid & 15;
    const int lsel = lid >> 4;
    const int lx   = lrow & 7;
    const uint32_t aBase = sb + (uint32_t)((wm + lrow) * 128);
    const uint32_t bBase = sb + A_SZ + (uint32_t)((wn + lrow) * 128);

    float acc[2][4][4] = {};
    const int nch = K >> 6;            // K/64

    ISSUE_STAGE(0, 0); cp_commit();
    ISSUE_STAGE(1, 1); cp_commit();

    for (int c = 0; c < nch; ++c) {
        cp_wait<1>();
        __syncthreads();
        int cl = c + 2;
        if (cl < nch) { ISSUE_STAGE(cl % NSTG, cl); }
        cp_commit();

        const uint32_t stg = (uint32_t)((c % NSTG) * STAGE_BYTES);

#pragma unroll
        for (int ks = 0; ks < 4; ++ks) {
            const uint32_t sw = (uint32_t)(((ks * 2 + lsel) ^ lx) << 4);
            uint32_t a[2][4], b[2][4];
#pragma unroll
            for (int mt = 0; mt < 2; mt++)
                ldmat_x4(a[mt], aBase + stg + (uint32_t)(mt * 2048) + sw);
#pragma unroll
            for (int j = 0; j < 2; j++)
                ldmat_x4(b[j], bBase + stg + (uint32_t)(j * 2048) + sw);
#pragma unroll
            for (int mt = 0; mt < 2; mt++)
#pragma unroll
                for (int nt = 0; nt < 4; nt++)
                    mma_f16(acc[mt][nt], a[mt],
                            b[nt >> 1][nt & 1], b[nt >> 1][2 + (nt & 1)]);
        }
    }

    // epilogue
#pragma unroll
    for (int mt = 0; mt < 2; mt++) {
        const size_t m1 = (size_t)m0 + wm + mt * 16 + g;
        const size_t m2 = m1 + 8;
#pragma unroll
        for (int nt = 0; nt < 4; nt++) {
            const int n = n0 + wn + nt * 8 + 2 * t;
            float2 v0 = make_float2(acc[mt][nt][0], acc[mt][nt][1]);
            float2 v1 = make_float2(acc[mt][nt][2], acc[mt][nt][3]);
            if (BIAS) {
                float2 bb = *(const float2*)(bias + n);
                v0.x += bb.x; v0.y += bb.y; v1.x += bb.x; v1.y += bb.y;
            }
            if (RESID) {
                float2 r0 = *(const float2*)(resid + m1 * N + n);
                float2 r1 = *(const float2*)(resid + m2 * N + n);
                v0.x += r0.x; v0.y += r0.y; v1.x += r1.x; v1.y += r1.y;
            }
            if (RELU) {
                v0.x = fmaxf(v0.x, 0.f); v0.y = fmaxf(v0.y, 0.f);
                v1.x = fmaxf(v1.x, 0.f); v1.y = fmaxf(v1.y, 0.f);
            }
            if (OUTH) {
                __half* Cout = (__half*)CoutV;
                *(__half2*)(Cout + m1 * N + n) = __float22half2_rn(v0);
                *(__half2*)(Cout + m2 * N + n) = __float22half2_rn(v1);
            } else {
                float* Cout = (float*)CoutV;
                *(float2*)(Cout + m1 * N + n) = v0;
                *(float2*)(Cout + m2 * N + n) = v1;
            }
        }
    }
}

// ---------------------------------------------------------------------------
// Weight packing (per call; small)
// ---------------------------------------------------------------------------
__global__ void pack_qkvT_kernel(const float* __restrict__ Wq,
                                 const float* __restrict__ Wk,
                                 const float* __restrict__ Wv)
{
    size_t i = (size_t)blockIdx.x * blockDim.x + threadIdx.x;
    const size_t total = (size_t)LL * QKVN * CC;
    if (i >= total) return;
    int k = (int)(i % CC);
    int n = (int)((i / CC) % QKVN);
    int l = (int)(i / ((size_t)CC * QKVN));
    int s = n / CC;
    int h = (n % CC) / DH;
    int d = n % DH;
    const float* W = (s == 0) ? Wq : (s == 1) ? Wk : Wv;
    g_wqkvT[i] = __float2half(W[(((size_t)l * HH + h) * CC + k) * DH + d]);
}

__global__ void transposeW_kernel(const float* __restrict__ W, __half* __restrict__ O,
                                  int Kd, int Nd)
{
    size_t i = (size_t)blockIdx.x * blockDim.x + threadIdx.x;
    size_t total = (size_t)LL * Kd * Nd;
    if (i >= total) return;
    int n = (int)(i % Nd);
    int k = (int)((i / Nd) % Kd);
    int l = (int)(i / ((size_t)Nd * Kd));
    O[((size_t)l * Nd + n) * Kd + k] = __float2half(W[i]);
}

// ---------------------------------------------------------------------------
// Warp LN core: vals = 6 float2 (cols 2*(lane+32*i)), returns mean/rstd
// ---------------------------------------------------------------------------
__device__ __forceinline__ void warp_ln_stats(const float2* v, float& mean, float& rinv)
{
    float s = 0.f, ss = 0.f;
#pragma unroll
    for (int i = 0; i < 6; i++) {
        s  += v[i].x + v[i].y;
        ss += v[i].x * v[i].x + v[i].y * v[i].y;
    }
#pragma unroll
    for (int o = 16; o; o >>= 1) {
        s  += __shfl_xor_sync(0xffffffffu, s,  o);
        ss += __shfl_xor_sync(0xffffffffu, ss, o);
    }
    mean = s * (1.f / CC);
    float var = ss * (1.f / CC) - mean * mean;
    rinv = rsqrtf(var + 1e-5f);
}

// ---------------------------------------------------------------------------
// LayerNorm: warp per row, vectorized; half or float output
// ---------------------------------------------------------------------------
template<bool OUTH>
__global__ void ln_kernel(const float* __restrict__ x,
                          const float* __restrict__ g,
                          const float* __restrict__ b,
                          void* __restrict__ outV)
{
    int row  = blockIdx.x * 8 + (threadIdx.x >> 5);
    int lane = threadIdx.x & 31;
    const float2* xr = (const float2*)(x + (size_t)row * CC);
    const float2* gg = (const float2*)g;
    const float2* bb = (const float2*)b;
    float2 v[6];
#pragma unroll
    for (int i = 0; i < 6; i++) v[i] = xr[lane + 32 * i];
    float mean, rinv;
    warp_ln_stats(v, mean, rinv);
#pragma unroll
    for (int i = 0; i < 6; i++) {
        float2 gv = gg[lane + 32 * i], bv = bb[lane + 32 * i];
        float2 o;
        o.x = (v[i].x - mean) * rinv * gv.x + bv.x;
        o.y = (v[i].y - mean) * rinv * gv.y + bv.y;
        if (OUTH) ((__half2*)outV)[(size_t)row * (CC/2) + lane + 32 * i] = __float22half2_rn(o);
        else      ((float2*)outV)[(size_t)row * (CC/2) + lane + 32 * i] = o;
    }
}

// ---------------------------------------------------------------------------
// Fused embedding + first LayerNorm: writes x (fp32) and ha (half)
// ---------------------------------------------------------------------------
__global__ void embed_ln_kernel(const int* __restrict__ idx,
                                const float* __restrict__ tok,
                                const float* __restrict__ pos,
                                const float* __restrict__ g,
                                const float* __restrict__ b)
{
    int row  = blockIdx.x * 8 + (threadIdx.x >> 5);
    int lane = threadIdx.x & 31;
    int t = row % TT;
    const float2* tr = (const float2*)(tok + (size_t)idx[row] * CC);
    const float2* pr = (const float2*)(pos + (size_t)t * CC);
    const float2* gg = (const float2*)g;
    const float2* bb = (const float2*)b;
    float2 v[6];
    float2* xo = (float2*)(g_x + (size_t)row * CC);
#pragma unroll
    for (int i = 0; i < 6; i++) {
        float2 a = tr[lane + 32 * i], p = pr[lane + 32 * i];
        v[i] = make_float2(a.x + p.x, a.y + p.y);
        xo[lane + 32 * i] = v[i];
    }
    float mean, rinv;
    warp_ln_stats(v, mean, rinv);
    __half2* ho = (__half2*)g_ha + (size_t)row * (CC/2);
#pragma unroll
    for (int i = 0; i < 6; i++) {
        float2 gv = gg[lane + 32 * i], bv = bb[lane + 32 * i];
        float2 o;
        o.x = (v[i].x - mean) * rinv * gv.x + bv.x;
        o.y = (v[i].y - mean) * rinv * gv.y + bv.y;
        ho[lane + 32 * i] = __float22half2_rn(o);
    }
}

// ---------------------------------------------------------------------------
// Attention: one block per (b,h). K stored transposed in smem (bank-conflict
// free S-phase); warp-per-row softmax; fp32 qkv in, half out.
// ---------------------------------------------------------------------------
__global__ __launch_bounds__(256)
void attn_kernel(const float* __restrict__ qkv, __half* __restrict__ o)
{
    __shared__ float Qs[32][64], Kt[64][33], Vs[32][64], Ss[32][33];

    int bh = blockIdx.x;
    int b  = bh / HH;
    int h  = bh % HH;
    int tid = threadIdx.x;

    // load: 32 rows x 16 float4
    for (int i = tid; i < 32 * 16; i += 256) {
        int t = i >> 4, d4 = i & 15;
        size_t base = (size_t)(b * TT + t) * QKVN + h * DH;
        float4 q = *((const float4*)(qkv + base) + d4);
        float4 k = *((const float4*)(qkv + base + CC) + d4);
        float4 v = *((const float4*)(qkv + base + 2 * CC) + d4);
        ((float4*)Qs[t])[d4] = q;
        ((float4*)Vs[t])[d4] = v;
        int d = d4 * 4;
        Kt[d][t] = k.x; Kt[d + 1][t] = k.y; Kt[d + 2][t] = k.z; Kt[d + 3][t] = k.w;
    }
    __syncthreads();

    // S = Q K^T * scale (causal). t warp-uniform, s = lane.
    {
        int t = tid >> 5, s = tid & 31;
#pragma unroll
        for (int r = 0; r < 4; r++) {
            int tt = t + 8 * r;
            float acc = 0.f;
            if (s <= tt) {
#pragma unroll 16
                for (int d = 0; d < 64; d++) acc += Qs[tt][d] * Kt[d][s];
                acc *= 0.125f;
            }
            Ss[tt][s] = acc;
        }
    }
    __syncthreads();

    // softmax: warp per row group (8 warps x 4 rows), lane = s
    {
        int wid = tid >> 5, lane = tid & 31;
#pragma unroll
        for (int r = 0; r < 4; r++) {
            int t = wid * 4 + r;
            float p = (lane <= t) ? Ss[t][lane] : -1e30f;
            float m = p;
#pragma unroll
            for (int off = 16; off; off >>= 1)
                m = fmaxf(m, __shfl_xor_sync(0xffffffffu, m, off));
            float e = (lane <= t) ? __expf(p - m) : 0.f;
            float sum = e;
#pragma unroll
            for (int off = 16; off; off >>= 1)
                sum += __shfl_xor_sync(0xffffffffu, sum, off);
            Ss[t][lane] = e * (1.f / sum);
        }
    }
    __syncthreads();

    // O = P V (t warp-uniform; Ss broadcast, Vs coalesced)
    for (int i = tid; i < 2048; i += 256) {
        int t = i >> 6, d = i & 63;
        float acc = 0.f;
        for (int s = 0; s <= t; s++) acc += Ss[t][s] * Vs[s][d];
        o[(size_t)(b * TT + t) * CC + h * DH + d] = __float2half(acc);
    }
}

// ---------------------------------------------------------------------------
// LM head: out[n,v] = h[n,:] @ Wlm[:,v] + blm[v]   (V=80, K=384), fp32
// ---------------------------------------------------------------------------
__global__ __launch_bounds__(640)
void lmhead_kernel(const float* __restrict__ h,
                   const float* __restrict__ Wlm,
                   const float* __restrict__ blm,
                   float* __restrict__ out)
{
    __shared__ float hs[8][CC];
    int tid  = threadIdx.x;
    int row0 = blockIdx.x * 8;
    for (int i = tid; i < 8 * CC; i += 640)
        hs[i / CC][i % CC] = h[(size_t)(row0 + i / CC) * CC + (i % CC)];
    __syncthreads();

    int v = tid % VV;
    int t = tid / VV;
    float acc = blm[v];
#pragma unroll 4
    for (int c = 0; c < CC; c++)
        acc += hs[t][c] * Wlm[(size_t)c * VV + v];
    out[(size_t)(row0 + t) * VV + v] = acc;
}

// ---------------------------------------------------------------------------
// Host launcher
// ---------------------------------------------------------------------------
extern "C" void kernel_launch(void* const* d_in, const int* in_sizes, int n_in,
                              void* d_out, int out_size)
{
    (void)in_sizes; (void)n_in; (void)out_size;
    const int*   idx  = (const int*)  d_in[0];
    const float* tok  = (const float*)d_in[1];
    const float* pos  = (const float*)d_in[2];
    const float* ln1g = (const float*)d_in[3];
    const float* ln1b = (const float*)d_in[4];
    const float* Wq   = (const float*)d_in[5];
    const float* Wk   = (const float*)d_in[6];
    const float* Wv   = (const float*)d_in[7];
    const float* Wo   = (const float*)d_in[8];
    const float* bo   = (const float*)d_in[9];
    const float* ln2g = (const float*)d_in[10];
    const float* ln2b = (const float*)d_in[11];
    const float* W1   = (const float*)d_in[12];
    const float* b1   = (const float*)d_in[13];
    const float* W2   = (const float*)d_in[14];
    const float* b2   = (const float*)d_in[15];
    const float* lnfg = (const float*)d_in[16];
    const float* lnfb = (const float*)d_in[17];
    const float* Wlm  = (const float*)d_in[18];
    const float* blm  = (const float*)d_in[19];
    float* out = (float*)d_out;

    float *px, *pqkv, *phf;
    __half *pha, *po, *phid, *pwqkvT, *pwoT, *pw1T, *pw2T;
    cudaGetSymbolAddress((void**)&px,     g_x);
    cudaGetSymbolAddress((void**)&pqkv,   g_qkv);
    cudaGetSymbolAddress((void**)&phf,    g_hf);
    cudaGetSymbolAddress((void**)&pha,    g_ha);
    cudaGetSymbolAddress((void**)&po,     g_o);
    cudaGetSymbolAddress((void**)&phid,   g_hid);
    cudaGetSymbolAddress((void**)&pwqkvT, g_wqkvT);
    cudaGetSymbolAddress((void**)&pwoT,   g_woT);
    cudaGetSymbolAddress((void**)&pw1T,   g_w1T);
    cudaGetSymbolAddress((void**)&pw2T,   g_w2T);

    cudaFuncSetAttribute(mma_gemm<false, false, false, false>,
                         cudaFuncAttributeMaxDynamicSharedMemorySize, DYN_SMEM);
    cudaFuncSetAttribute(mma_gemm<true, false, true, false>,
                         cudaFuncAttributeMaxDynamicSharedMemorySize, DYN_SMEM);
    cudaFuncSetAttribute(mma_gemm<true, true, false, true>,
                         cudaFuncAttributeMaxDynamicSharedMemorySize, DYN_SMEM);

    // pack half weights
    {
        size_t t1 = (size_t)LL * QKVN * CC;
        pack_qkvT_kernel<<<(int)((t1 + 255) / 256), 256>>>(Wq, Wk, Wv);
        size_t t2 = (size_t)LL * CC * CC;
        transposeW_kernel<<<(int)((t2 + 255) / 256), 256>>>(Wo, pwoT, CC, CC);
        size_t t3 = (size_t)LL * CC * C4;
        transposeW_kernel<<<(int)((t3 + 255) / 256), 256>>>(W1, pw1T, CC, C4);
        size_t t4 = (size_t)LL * C4 * CC;
        transposeW_kernel<<<(int)((t4 + 255) / 256), 256>>>(W2, pw2T, C4, CC);
    }
    // embeddings + ln1 of layer 0 (fused)
    embed_ln_kernel<<<NT / 8, 256>>>(idx, tok, pos, ln1g, ln1b);

    const int MBLK = NT / 128;   // 1024
    for (int l = 0; l < LL; l++) {
        // ln1 -> half (layer 0 already done by embed_ln)
        if (l > 0)
            ln_kernel<true><<<NT / 8, 256>>>(px, ln1g + (size_t)l * CC, ln1b + (size_t)l * CC, pha);
        // qkv = h @ Wqkv   [NT,1152] fp32 out
        mma_gemm<false, false, false, false><<<dim3(QKVN / 128, MBLK), 512, DYN_SMEM>>>(
            pha, pwqkvT + (size_t)l * QKVN * CC, nullptr, nullptr, pqkv, QKVN, CC);
        // attention (fp32 in, half out)
        attn_kernel<<<BB * HH, 256>>>(pqkv, po);
        // x = x + o @ Wo + bo  (fp32 out)
        mma_gemm<true, false, true, false><<<dim3(CC / 128, MBLK), 512, DYN_SMEM>>>(
            po, pwoT + (size_t)l * CC * CC, bo + (size_t)l * CC, px, px, CC, CC);
        // ln2 -> half
        ln_kernel<true><<<NT / 8, 256>>>(px, ln2g + (size_t)l * CC, ln2b + (size_t)l * CC, pha);
        // hid = relu(h @ W1 + b1)   [NT,1536] half out
        mma_gemm<true, true, false, true><<<dim3(C4 / 128, MBLK), 512, DYN_SMEM>>>(
            pha, pw1T + (size_t)l * C4 * CC, b1 + (size_t)l * C4, nullptr, phid, C4, CC);
        // x = x + hid @ W2 + b2  (fp32 out)
        mma_gemm<true, false, true, false><<<dim3(CC / 128, MBLK), 512, DYN_SMEM>>>(
            phid, pw2T + (size_t)l * CC * C4, b2 + (size_t)l * CC, px, px, CC, C4);
    }
    // final LN (fp32) + LM head
    ln_kernel<false><<<NT / 8, 256>>>(px, lnfg, lnfb, phf);
    lmhead_kernel<<<NT / 8, 640>>>(phf, Wlm, blm, out);
}

// round 14
// speedup vs baseline: 1.1035x; 1.1035x over previous
#include <cuda_runtime.h>
#include <cuda_fp16.h>
#include <cstdint>

// Problem constants
#define BB 4096
#define TT 32
#define CC 384
#define HH 6
#define DH 64
#define LL 6
#define VV 80
#define NT (BB*TT)          // 131072 tokens
#define C4 (4*CC)           // 1536
#define QKVN (3*CC)         // 1152

// ---------------------------------------------------------------------------
// Scratch (static device globals; no runtime allocation allowed)
// ---------------------------------------------------------------------------
__device__ float  g_x   [(size_t)NT * CC];      // residual stream (fp32)
__device__ float  g_qkv [(size_t)NT * QKVN];    // q|k|v (fp32, attention input)
__device__ float  g_hf  [(size_t)NT * CC];      // final LN output (fp32)
__device__ __half g_ha  [(size_t)NT * CC];      // layer LN output (half, GEMM A)
__device__ __half g_o   [(size_t)NT * CC];      // attention output (half)
__device__ __half g_hid [(size_t)NT * C4];      // MLP hidden (half)
// Transposed (K-major, [N][K]) half weights
__device__ __half g_wqkvT[(size_t)LL * QKVN * CC];
__device__ __half g_woT  [(size_t)LL * CC * CC];
__device__ __half g_w1T  [(size_t)LL * C4 * CC];
__device__ __half g_w2T  [(size_t)LL * CC * C4];

// ---------------------------------------------------------------------------
// PTX helpers (sm_80+ baseline — no 'a'-variant instructions)
// ---------------------------------------------------------------------------
__device__ __forceinline__ uint32_t smem_u32(const void* p) {
    return (uint32_t)__cvta_generic_to_shared(p);
}
__device__ __forceinline__ void cp_async16(uint32_t s, const void* g) {
    asm volatile("cp.async.cg.shared.global [%0], [%1], 16;" :: "r"(s), "l"(g));
}
__device__ __forceinline__ void cp_commit() {
    asm volatile("cp.async.commit_group;" ::: "memory");
}
template<int N> __device__ __forceinline__ void cp_wait() {
    asm volatile("cp.async.wait_group %0;" :: "n"(N) : "memory");
}
__device__ __forceinline__ void ldmat_x4(uint32_t* r, uint32_t addr) {
    asm volatile("ldmatrix.sync.aligned.m8n8.x4.shared.b16 {%0,%1,%2,%3}, [%4];"
                 : "=r"(r[0]), "=r"(r[1]), "=r"(r[2]), "=r"(r[3]) : "r"(addr));
}
__device__ __forceinline__ void mma_f16(float* d, const uint32_t* a, uint32_t b0, uint32_t b1) {
    asm volatile(
        "mma.sync.aligned.m16n8k16.row.col.f32.f16.f16.f32 "
        "{%0,%1,%2,%3}, {%4,%5,%6,%7}, {%8,%9}, {%0,%1,%2,%3};"
        : "+f"(d[0]), "+f"(d[1]), "+f"(d[2]), "+f"(d[3])
        : "r"(a[0]), "r"(a[1]), "r"(a[2]), "r"(a[3]), "r"(b0), "r"(b1));
}

// ---------------------------------------------------------------------------
// fp16 ldmatrix GEMM: CTA 256x128, BK=64, 3-stage cp.async, 256 threads,
// 8 warps (4 M x 2 N), warp tile 64x64. Cuts SMEM bytes/MAC by 31% vs
// 128x128 (the crossbar is the binding resource). ~185 regs — no spills.
// ---------------------------------------------------------------------------
#define A_SZ 32768                 // 256 rows * 128B
#define B_SZ 16384                 // 128 rows * 128B
#define STAGE_BYTES (A_SZ + B_SZ)  // 49152
#define NSTG 3
#define DYN_SMEM (NSTG*STAGE_BYTES)  // 147456

#define ISSUE_STAGE(buf, ch) do {                                            \
    uint32_t bA_ = sb + (uint32_t)(buf) * STAGE_BYTES + offA0;               \
    uint32_t bB_ = bA_ + A_SZ;                                               \
    const __half* pa_ = pA0 + (size_t)(ch) * 64;                             \
    const __half* pb_ = pB0 + (size_t)(ch) * 64;                             \
    _Pragma("unroll")                                                        \
    for (int i_ = 0; i_ < 8; i_++) {                                         \
        cp_async16(bA_ + (uint32_t)(i_ * 4096), pa_);                        \
        pa_ += kstep;                                                        \
    }                                                                        \
    _Pragma("unroll")                                                        \
    for (int i_ = 0; i_ < 4; i_++) {                                         \
        cp_async16(bB_ + (uint32_t)(i_ * 4096), pb_);                        \
        pb_ += kstep;                                                        \
    }                                                                        \
} while (0)

template<bool BIAS, bool RELU, bool RESID, bool OUTH>
__global__ __launch_bounds__(256)
void mma_gemm(const __half* __restrict__ A, const __half* __restrict__ Bt,
              const float* __restrict__ bias, const float* __restrict__ resid,
              void* __restrict__ CoutV, int N, int K)
{
    extern __shared__ char smem[];
    const uint32_t sb = smem_u32(smem);
    const int tid = threadIdx.x;
    const int wid = tid >> 5, lid = tid & 31;
    const int m0 = blockIdx.y * 256;
    const int n0 = blockIdx.x * 128;
    const int wm = (wid & 3) * 64;     // warp M offset (4 warps over 256)
    const int wn = (wid >> 2) * 64;    // warp N offset (2 warps over 128)
    const int g  = lid >> 2;           // groupID
    const int t  = lid & 3;            // thread-in-group

    // cp.async mapping: rows (tid>>3)+32i, 16B chunk col tid&7.
    const int row0 = tid >> 3;         // 0..31
    const int ccol = tid & 7;
    const uint32_t offA0 = (uint32_t)(row0 * 128 + ((ccol ^ (row0 & 7)) << 4));
    const __half* pA0 = A  + (size_t)(m0 + row0) * K + ccol * 8;
    const __half* pB0 = Bt + (size_t)(n0 + row0) * K + ccol * 8;
    const size_t kstep = (size_t)32 * K;

    // ldmatrix per-lane addressing
    const int lrow = lid & 15;
    const int lsel = lid >> 4;
    const int lx   = lrow & 7;
    const uint32_t aBase = sb + (uint32_t)((wm + lrow) * 128);
    const uint32_t bBase = sb + A_SZ + (uint32_t)((wn + lrow) * 128);

    float acc[4][8][4] = {};
    const int nch = K >> 6;            // K/64

    ISSUE_STAGE(0, 0); cp_commit();
    ISSUE_STAGE(1, 1); cp_commit();

    for (int c = 0; c < nch; ++c) {
        cp_wait<1>();
        __syncthreads();
        int cl = c + 2;
        if (cl < nch) { ISSUE_STAGE(cl % NSTG, cl); }
        cp_commit();

        const uint32_t stg = (uint32_t)((c % NSTG) * STAGE_BYTES);

#pragma unroll
        for (int ks = 0; ks < 4; ++ks) {
            const uint32_t sw = (uint32_t)(((ks * 2 + lsel) ^ lx) << 4);
            uint32_t a[4][4], b[4][4];
#pragma unroll
            for (int mt = 0; mt < 4; mt++)
                ldmat_x4(a[mt], aBase + stg + (uint32_t)(mt * 2048) + sw);
#pragma unroll
            for (int j = 0; j < 4; j++)
                ldmat_x4(b[j], bBase + stg + (uint32_t)(j * 2048) + sw);
#pragma unroll
            for (int mt = 0; mt < 4; mt++)
#pragma unroll
                for (int nt = 0; nt < 8; nt++)
                    mma_f16(acc[mt][nt], a[mt],
                            b[nt >> 1][nt & 1], b[nt >> 1][2 + (nt & 1)]);
        }
    }

    // epilogue
#pragma unroll
    for (int mt = 0; mt < 4; mt++) {
        const size_t m1 = (size_t)m0 + wm + mt * 16 + g;
        const size_t m2 = m1 + 8;
#pragma unroll
        for (int nt = 0; nt < 8; nt++) {
            const int n = n0 + wn + nt * 8 + 2 * t;
            float2 v0 = make_float2(acc[mt][nt][0], acc[mt][nt][1]);
            float2 v1 = make_float2(acc[mt][nt][2], acc[mt][nt][3]);
            if (BIAS) {
                float2 bb = *(const float2*)(bias + n);
                v0.x += bb.x; v0.y += bb.y; v1.x += bb.x; v1.y += bb.y;
            }
            if (RESID) {
                float2 r0 = *(const float2*)(resid + m1 * N + n);
                float2 r1 = *(const float2*)(resid + m2 * N + n);
                v0.x += r0.x; v0.y += r0.y; v1.x += r1.x; v1.y += r1.y;
            }
            if (RELU) {
                v0.x = fmaxf(v0.x, 0.f); v0.y = fmaxf(v0.y, 0.f);
                v1.x = fmaxf(v1.x, 0.f); v1.y = fmaxf(v1.y, 0.f);
            }
            if (OUTH) {
                __half* Cout = (__half*)CoutV;
                *(__half2*)(Cout + m1 * N + n) = __float22half2_rn(v0);
                *(__half2*)(Cout + m2 * N + n) = __float22half2_rn(v1);
            } else {
                float* Cout = (float*)CoutV;
                *(float2*)(Cout + m1 * N + n) = v0;
                *(float2*)(Cout + m2 * N + n) = v1;
            }
        }
    }
}

// ---------------------------------------------------------------------------
// Weight packing (per call; small)
// ---------------------------------------------------------------------------
__global__ void pack_qkvT_kernel(const float* __restrict__ Wq,
                                 const float* __restrict__ Wk,
                                 const float* __restrict__ Wv)
{
    size_t i = (size_t)blockIdx.x * blockDim.x + threadIdx.x;
    const size_t total = (size_t)LL * QKVN * CC;
    if (i >= total) return;
    int k = (int)(i % CC);
    int n = (int)((i / CC) % QKVN);
    int l = (int)(i / ((size_t)CC * QKVN));
    int s = n / CC;
    int h = (n % CC) / DH;
    int d = n % DH;
    const float* W = (s == 0) ? Wq : (s == 1) ? Wk : Wv;
    g_wqkvT[i] = __float2half(W[(((size_t)l * HH + h) * CC + k) * DH + d]);
}

__global__ void transposeW_kernel(const float* __restrict__ W, __half* __restrict__ O,
                                  int Kd, int Nd)
{
    size_t i = (size_t)blockIdx.x * blockDim.x + threadIdx.x;
    size_t total = (size_t)LL * Kd * Nd;
    if (i >= total) return;
    int n = (int)(i % Nd);
    int k = (int)((i / Nd) % Kd);
    int l = (int)(i / ((size_t)Nd * Kd));
    O[((size_t)l * Nd + n) * Kd + k] = __float2half(W[i]);
}

// ---------------------------------------------------------------------------
// Warp LN core: vals = 6 float2 (cols 2*(lane+32*i)), returns mean/rstd
// ---------------------------------------------------------------------------
__device__ __forceinline__ void warp_ln_stats(const float2* v, float& mean, float& rinv)
{
    float s = 0.f, ss = 0.f;
#pragma unroll
    for (int i = 0; i < 6; i++) {
        s  += v[i].x + v[i].y;
        ss += v[i].x * v[i].x + v[i].y * v[i].y;
    }
#pragma unroll
    for (int o = 16; o; o >>= 1) {
        s  += __shfl_xor_sync(0xffffffffu, s,  o);
        ss += __shfl_xor_sync(0xffffffffu, ss, o);
    }
    mean = s * (1.f / CC);
    float var = ss * (1.f / CC) - mean * mean;
    rinv = rsqrtf(var + 1e-5f);
}

// ---------------------------------------------------------------------------
// LayerNorm: warp per row, vectorized; half or float output
// ---------------------------------------------------------------------------
template<bool OUTH>
__global__ void ln_kernel(const float* __restrict__ x,
                          const float* __restrict__ g,
                          const float* __restrict__ b,
                          void* __restrict__ outV)
{
    int row  = blockIdx.x * 8 + (threadIdx.x >> 5);
    int lane = threadIdx.x & 31;
    const float2* xr = (const float2*)(x + (size_t)row * CC);
    const float2* gg = (const float2*)g;
    const float2* bb = (const float2*)b;
    float2 v[6];
#pragma unroll
    for (int i = 0; i < 6; i++) v[i] = xr[lane + 32 * i];
    float mean, rinv;
    warp_ln_stats(v, mean, rinv);
#pragma unroll
    for (int i = 0; i < 6; i++) {
        float2 gv = gg[lane + 32 * i], bv = bb[lane + 32 * i];
        float2 o;
        o.x = (v[i].x - mean) * rinv * gv.x + bv.x;
        o.y = (v[i].y - mean) * rinv * gv.y + bv.y;
        if (OUTH) ((__half2*)outV)[(size_t)row * (CC/2) + lane + 32 * i] = __float22half2_rn(o);
        else      ((float2*)outV)[(size_t)row * (CC/2) + lane + 32 * i] = o;
    }
}

// ---------------------------------------------------------------------------
// Fused embedding + first LayerNorm: writes x (fp32) and ha (half)
// ---------------------------------------------------------------------------
__global__ void embed_ln_kernel(const int* __restrict__ idx,
                                const float* __restrict__ tok,
                                const float* __restrict__ pos,
                                const float* __restrict__ g,
                                const float* __restrict__ b)
{
    int row  = blockIdx.x * 8 + (threadIdx.x >> 5);
    int lane = threadIdx.x & 31;
    int t = row % TT;
    const float2* tr = (const float2*)(tok + (size_t)idx[row] * CC);
    const float2* pr = (const float2*)(pos + (size_t)t * CC);
    const float2* gg = (const float2*)g;
    const float2* bb = (const float2*)b;
    float2 v[6];
    float2* xo = (float2*)(g_x + (size_t)row * CC);
#pragma unroll
    for (int i = 0; i < 6; i++) {
        float2 a = tr[lane + 32 * i], p = pr[lane + 32 * i];
        v[i] = make_float2(a.x + p.x, a.y + p.y);
        xo[lane + 32 * i] = v[i];
    }
    float mean, rinv;
    warp_ln_stats(v, mean, rinv);
    __half2* ho = (__half2*)g_ha + (size_t)row * (CC/2);
#pragma unroll
    for (int i = 0; i < 6; i++) {
        float2 gv = gg[lane + 32 * i], bv = bb[lane + 32 * i];
        float2 o;
        o.x = (v[i].x - mean) * rinv * gv.x + bv.x;
        o.y = (v[i].y - mean) * rinv * gv.y + bv.y;
        ho[lane + 32 * i] = __float22half2_rn(o);
    }
}

// ---------------------------------------------------------------------------
// Attention: one block per (b,h). K stored transposed in smem (bank-conflict
// free S-phase); warp-per-row softmax; fp32 qkv in, half out.
// ---------------------------------------------------------------------------
__global__ __launch_bounds__(256)
void attn_kernel(const float* __restrict__ qkv, __half* __restrict__ o)
{
    __shared__ float Qs[32][64], Kt[64][33], Vs[32][64], Ss[32][33];

    int bh = blockIdx.x;
    int b  = bh / HH;
    int h  = bh % HH;
    int tid = threadIdx.x;

    // load: 32 rows x 16 float4
    for (int i = tid; i < 32 * 16; i += 256) {
        int t = i >> 4, d4 = i & 15;
        size_t base = (size_t)(b * TT + t) * QKVN + h * DH;
        float4 q = *((const float4*)(qkv + base) + d4);
        float4 k = *((const float4*)(qkv + base + CC) + d4);
        float4 v = *((const float4*)(qkv + base + 2 * CC) + d4);
        ((float4*)Qs[t])[d4] = q;
        ((float4*)Vs[t])[d4] = v;
        int d = d4 * 4;
        Kt[d][t] = k.x; Kt[d + 1][t] = k.y; Kt[d + 2][t] = k.z; Kt[d + 3][t] = k.w;
    }
    __syncthreads();

    // S = Q K^T * scale (causal). t warp-uniform, s = lane.
    {
        int t = tid >> 5, s = tid & 31;
#pragma unroll
        for (int r = 0; r < 4; r++) {
            int tt = t + 8 * r;
            float acc = 0.f;
            if (s <= tt) {
#pragma unroll 16
                for (int d = 0; d < 64; d++) acc += Qs[tt][d] * Kt[d][s];
                acc *= 0.125f;
            }
            Ss[tt][s] = acc;
        }
    }
    __syncthreads();

    // softmax: warp per row group (8 warps x 4 rows), lane = s
    {
        int wid = tid >> 5, lane = tid & 31;
#pragma unroll
        for (int r = 0; r < 4; r++) {
            int t = wid * 4 + r;
            float p = (lane <= t) ? Ss[t][lane] : -1e30f;
            float m = p;
#pragma unroll
            for (int off = 16; off; off >>= 1)
                m = fmaxf(m, __shfl_xor_sync(0xffffffffu, m, off));
            float e = (lane <= t) ? __expf(p - m) : 0.f;
            float sum = e;
#pragma unroll
            for (int off = 16; off; off >>= 1)
                sum += __shfl_xor_sync(0xffffffffu, sum, off);
            Ss[t][lane] = e * (1.f / sum);
        }
    }
    __syncthreads();

    // O = P V (t warp-uniform; Ss broadcast, Vs coalesced)
    for (int i = tid; i < 2048; i += 256) {
        int t = i >> 6, d = i & 63;
        float acc = 0.f;
        for (int s = 0; s <= t; s++) acc += Ss[t][s] * Vs[s][d];
        o[(size_t)(b * TT + t) * CC + h * DH + d] = __float2half(acc);
    }
}

// ---------------------------------------------------------------------------
// LM head: out[n,v] = h[n,:] @ Wlm[:,v] + blm[v]   (V=80, K=384), fp32
// ---------------------------------------------------------------------------
__global__ __launch_bounds__(640)
void lmhead_kernel(const float* __restrict__ h,
                   const float* __restrict__ Wlm,
                   const float* __restrict__ blm,
                   float* __restrict__ out)
{
    __shared__ float hs[8][CC];
    int tid  = threadIdx.x;
    int row0 = blockIdx.x * 8;
    for (int i = tid; i < 8 * CC; i += 640)
        hs[i / CC][i % CC] = h[(size_t)(row0 + i / CC) * CC + (i % CC)];
    __syncthreads();

    int v = tid % VV;
    int t = tid / VV;
    float acc = blm[v];
#pragma unroll 4
    for (int c = 0; c < CC; c++)
        acc += hs[t][c] * Wlm[(size_t)c * VV + v];
    out[(size_t)(row0 + t) * VV + v] = acc;
}

// ---------------------------------------------------------------------------
// Host launcher
// ---------------------------------------------------------------------------
extern "C" void kernel_launch(void* const* d_in, const int* in_sizes, int n_in,
                              void* d_out, int out_size)
{
    (void)in_sizes; (void)n_in; (void)out_size;
    const int*   idx  = (const int*)  d_in[0];
    const float* tok  = (const float*)d_in[1];
    const float* pos  = (const float*)d_in[2];
    const float* ln1g = (const float*)d_in[3];
    const float* ln1b = (const float*)d_in[4];
    const float* Wq   = (const float*)d_in[5];
    const float* Wk   = (const float*)d_in[6];
    const float* Wv   = (const float*)d_in[7];
    const float* Wo   = (const float*)d_in[8];
    const float* bo   = (const float*)d_in[9];
    const float* ln2g = (const float*)d_in[10];
    const float* ln2b = (const float*)d_in[11];
    const float* W1   = (const float*)d_in[12];
    const float* b1   = (const float*)d_in[13];
    const float* W2   = (const float*)d_in[14];
    const float* b2   = (const float*)d_in[15];
    const float* lnfg = (const float*)d_in[16];
    const float* lnfb = (const float*)d_in[17];
    const float* Wlm  = (const float*)d_in[18];
    const float* blm  = (const float*)d_in[19];
    float* out = (float*)d_out;

    float *px, *pqkv, *phf;
    __half *pha, *po, *phid, *pwqkvT, *pwoT, *pw1T, *pw2T;
    cudaGetSymbolAddress((void**)&px,     g_x);
    cudaGetSymbolAddress((void**)&pqkv,   g_qkv);
    cudaGetSymbolAddress((void**)&phf,    g_hf);
    cudaGetSymbolAddress((void**)&pha,    g_ha);
    cudaGetSymbolAddress((void**)&po,     g_o);
    cudaGetSymbolAddress((void**)&phid,   g_hid);
    cudaGetSymbolAddress((void**)&pwqkvT, g_wqkvT);
    cudaGetSymbolAddress((void**)&pwoT,   g_woT);
    cudaGetSymbolAddress((void**)&pw1T,   g_w1T);
    cudaGetSymbolAddress((void**)&pw2T,   g_w2T);

    cudaFuncSetAttribute(mma_gemm<false, false, false, false>,
                         cudaFuncAttributeMaxDynamicSharedMemorySize, DYN_SMEM);
    cudaFuncSetAttribute(mma_gemm<true, false, true, false>,
                         cudaFuncAttributeMaxDynamicSharedMemorySize, DYN_SMEM);
    cudaFuncSetAttribute(mma_gemm<true, true, false, true>,
                         cudaFuncAttributeMaxDynamicSharedMemorySize, DYN_SMEM);

    // pack half weights
    {
        size_t t1 = (size_t)LL * QKVN * CC;
        pack_qkvT_kernel<<<(int)((t1 + 255) / 256), 256>>>(Wq, Wk, Wv);
        size_t t2 = (size_t)LL * CC * CC;
        transposeW_kernel<<<(int)((t2 + 255) / 256), 256>>>(Wo, pwoT, CC, CC);
        size_t t3 = (size_t)LL * CC * C4;
        transposeW_kernel<<<(int)((t3 + 255) / 256), 256>>>(W1, pw1T, CC, C4);
        size_t t4 = (size_t)LL * C4 * CC;
        transposeW_kernel<<<(int)((t4 + 255) / 256), 256>>>(W2, pw2T, C4, CC);
    }
    // embeddings + ln1 of layer 0 (fused)
    embed_ln_kernel<<<NT / 8, 256>>>(idx, tok, pos, ln1g, ln1b);

    const int MBLK = NT / 256;   // 512
    for (int l = 0; l < LL; l++) {
        // ln1 -> half (layer 0 already done by embed_ln)
        if (l > 0)
            ln_kernel<true><<<NT / 8, 256>>>(px, ln1g + (size_t)l * CC, ln1b + (size_t)l * CC, pha);
        // qkv = h @ Wqkv   [NT,1152] fp32 out
        mma_gemm<false, false, false, false><<<dim3(QKVN / 128, MBLK), 256, DYN_SMEM>>>(
            pha, pwqkvT + (size_t)l * QKVN * CC, nullptr, nullptr, pqkv, QKVN, CC);
        // attention (fp32 in, half out)
        attn_kernel<<<BB * HH, 256>>>(pqkv, po);
        // x = x + o @ Wo + bo  (fp32 out)
        mma_gemm<true, false, true, false><<<dim3(CC / 128, MBLK), 256, DYN_SMEM>>>(
            po, pwoT + (size_t)l * CC * CC, bo + (size_t)l * CC, px, px, CC, CC);
        // ln2 -> half
        ln_kernel<true><<<NT / 8, 256>>>(px, ln2g + (size_t)l * CC, ln2b + (size_t)l * CC, pha);
        // hid = relu(h @ W1 + b1)   [NT,1536] half out
        mma_gemm<true, true, false, true><<<dim3(C4 / 128, MBLK), 256, DYN_SMEM>>>(
            pha, pw1T + (size_t)l * C4 * CC, b1 + (size_t)l * C4, nullptr, phid, C4, CC);
        // x = x + hid @ W2 + b2  (fp32 out)
        mma_gemm<true, false, true, false><<<dim3(CC / 128, MBLK), 256, DYN_SMEM>>>(
            phid, pw2T + (size_t)l * CC * C4, b2 + (size_t)l * CC, px, px, CC, C4);
    }
    // final LN (fp32) + LM head
    ln_kernel<false><<<NT / 8, 256>>>(px, lnfg, lnfb, phf);
    lmhead_kernel<<<NT / 8, 640>>>(phf, Wlm, blm, out);
}

// round 16
// speedup vs baseline: 1.3403x; 1.2146x over previous
#include <cuda_runtime.h>
#include <cuda_fp16.h>
#include <cstdint>

// Problem constants
#define BB 4096
#define TT 32
#define CC 384
#define HH 6
#define DH 64
#define LL 6
#define VV 80
#define NT (BB*TT)          // 131072 tokens
#define C4 (4*CC)           // 1536
#define QKVN (3*CC)         // 1152

// ---------------------------------------------------------------------------
// Scratch (static device globals; no runtime allocation allowed)
// ---------------------------------------------------------------------------
__device__ float  g_x   [(size_t)NT * CC];      // residual stream (fp32)
__device__ float  g_qkv [(size_t)NT * QKVN];    // q|k|v (fp32, attention input)
__device__ float  g_hf  [(size_t)NT * CC];      // final LN output (fp32)
__device__ __half g_ha  [(size_t)NT * CC];      // layer LN output (half, GEMM A)
__device__ __half g_o   [(size_t)NT * CC];      // attention output (half)
__device__ __half g_hid [(size_t)NT * C4];      // MLP hidden (half)
// Transposed (K-major, [N][K]) half weights
__device__ __half g_wqkvT[(size_t)LL * QKVN * CC];
__device__ __half g_woT  [(size_t)LL * CC * CC];
__device__ __half g_w1T  [(size_t)LL * C4 * CC];
__device__ __half g_w2T  [(size_t)LL * CC * C4];

// ---------------------------------------------------------------------------
// PTX helpers (sm_80+ baseline — no 'a'-variant instructions)
// ---------------------------------------------------------------------------
__device__ __forceinline__ uint32_t smem_u32(const void* p) {
    return (uint32_t)__cvta_generic_to_shared(p);
}
__device__ __forceinline__ void cp_async16(uint32_t s, const void* g) {
    asm volatile("cp.async.cg.shared.global [%0], [%1], 16;" :: "r"(s), "l"(g));
}
__device__ __forceinline__ void cp_commit() {
    asm volatile("cp.async.commit_group;" ::: "memory");
}
template<int N> __device__ __forceinline__ void cp_wait() {
    asm volatile("cp.async.wait_group %0;" :: "n"(N) : "memory");
}
__device__ __forceinline__ void ldmat_x4(uint32_t* r, uint32_t addr) {
    asm volatile("ldmatrix.sync.aligned.m8n8.x4.shared.b16 {%0,%1,%2,%3}, [%4];"
                 : "=r"(r[0]), "=r"(r[1]), "=r"(r[2]), "=r"(r[3]) : "r"(addr));
}
__device__ __forceinline__ void mma_f16(float* d, const uint32_t* a, uint32_t b0, uint32_t b1) {
    asm volatile(
        "mma.sync.aligned.m16n8k16.row.col.f32.f16.f16.f32 "
        "{%0,%1,%2,%3}, {%4,%5,%6,%7}, {%8,%9}, {%0,%1,%2,%3};"
        : "+f"(d[0]), "+f"(d[1]), "+f"(d[2]), "+f"(d[3])
        : "r"(a[0]), "r"(a[1]), "r"(a[2]), "r"(a[3]), "r"(b0), "r"(b1));
}

// ---------------------------------------------------------------------------
// fp16 ldmatrix GEMM (R11/R8 config — proven best): CTA 128x128, BK=64,
// 3-stage cp.async, 8 warps 2x4. DO NOT TOUCH (at legacy-HMMA rate ceiling).
// ---------------------------------------------------------------------------
#define A_SZ 16384                 // 128 rows * 128B
#define STAGE_BYTES 32768          // A + B
#define NSTG 3
#define DYN_SMEM (NSTG*STAGE_BYTES)  // 98304

#define ISSUE_STAGE(buf, ch) do {                                            \
    uint32_t bA_ = sb + (uint32_t)(buf) * STAGE_BYTES;                       \
    uint32_t bB_ = bA_ + A_SZ;                                               \
    _Pragma("unroll")                                                        \
    for (int i_ = 0; i_ < 4; i_++) {                                         \
        cp_async16(bA_ + offs[i_], gA[i_] + (size_t)(ch) * 64);              \
        cp_async16(bB_ + offs[i_], gB[i_] + (size_t)(ch) * 64);              \
    }                                                                        \
} while (0)

template<bool BIAS, bool RELU, bool RESID, bool OUTH>
__global__ __launch_bounds__(256)
void mma_gemm(const __half* __restrict__ A, const __half* __restrict__ Bt,
              const float* __restrict__ bias, const float* __restrict__ resid,
              void* __restrict__ CoutV, int N, int K)
{
    extern __shared__ char smem[];
    const uint32_t sb = smem_u32(smem);
    const int tid = threadIdx.x;
    const int wid = tid >> 5, lid = tid & 31;
    const int m0 = blockIdx.y * 128;
    const int n0 = blockIdx.x * 128;
    const int wm = (wid & 1) * 64;     // warp M offset
    const int wn = (wid >> 1) * 32;    // warp N offset
    const int g  = lid >> 2;           // groupID
    const int t  = lid & 3;            // thread-in-group

    // cp.async mapping: 1024 16B chunks per (A|B) tile, 4 per thread each.
    uint32_t offs[4];
    const __half* gA[4];
    const __half* gB[4];
#pragma unroll
    for (int i = 0; i < 4; i++) {
        int q   = tid + 256 * i;
        int row = q >> 3;              // 0..127
        int c   = q & 7;               // 16B chunk within 128B row
        offs[i] = (uint32_t)(row * 128 + ((c ^ (row & 7)) << 4));
        gA[i] = A  + (size_t)(m0 + row) * K + c * 8;
        gB[i] = Bt + (size_t)(n0 + row) * K + c * 8;
    }

    // ldmatrix per-lane addressing
    const int lrow = lid & 15;
    const int lsel = lid >> 4;
    const int lx   = lrow & 7;
    const uint32_t aBase = sb + (uint32_t)((wm + lrow) * 128);
    const uint32_t bBase = sb + A_SZ + (uint32_t)((wn + lrow) * 128);

    float acc[4][4][4] = {};
    const int nch = K >> 6;            // K/64

    ISSUE_STAGE(0, 0); cp_commit();
    ISSUE_STAGE(1, 1); cp_commit();

    for (int c = 0; c < nch; ++c) {
        cp_wait<1>();
        __syncthreads();
        int cl = c + 2;
        if (cl < nch) { ISSUE_STAGE(cl % NSTG, cl); }
        cp_commit();

        const uint32_t stg = (uint32_t)((c % NSTG) * STAGE_BYTES);

#pragma unroll
        for (int ks = 0; ks < 4; ++ks) {
            const uint32_t sw = (uint32_t)(((ks * 2 + lsel) ^ lx) << 4);
            uint32_t a[4][4], b[2][4];
#pragma unroll
            for (int mt = 0; mt < 4; mt++)
                ldmat_x4(a[mt], aBase + stg + (uint32_t)(mt * 2048) + sw);
            ldmat_x4(b[0], bBase + stg + sw);
            ldmat_x4(b[1], bBase + stg + 2048u + sw);
#pragma unroll
            for (int mt = 0; mt < 4; mt++)
#pragma unroll
                for (int nt = 0; nt < 4; nt++)
                    mma_f16(acc[mt][nt], a[mt],
                            b[nt >> 1][nt & 1], b[nt >> 1][2 + (nt & 1)]);
        }
    }

    // epilogue
#pragma unroll
    for (int mt = 0; mt < 4; mt++) {
        const size_t m1 = (size_t)m0 + wm + mt * 16 + g;
        const size_t m2 = m1 + 8;
#pragma unroll
        for (int nt = 0; nt < 4; nt++) {
            const int n = n0 + wn + nt * 8 + 2 * t;
            float2 v0 = make_float2(acc[mt][nt][0], acc[mt][nt][1]);
            float2 v1 = make_float2(acc[mt][nt][2], acc[mt][nt][3]);
            if (BIAS) {
                float2 bb = *(const float2*)(bias + n);
                v0.x += bb.x; v0.y += bb.y; v1.x += bb.x; v1.y += bb.y;
            }
            if (RESID) {
                float2 r0 = *(const float2*)(resid + m1 * N + n);
                float2 r1 = *(const float2*)(resid + m2 * N + n);
                v0.x += r0.x; v0.y += r0.y; v1.x += r1.x; v1.y += r1.y;
            }
            if (RELU) {
                v0.x = fmaxf(v0.x, 0.f); v0.y = fmaxf(v0.y, 0.f);
                v1.x = fmaxf(v1.x, 0.f); v1.y = fmaxf(v1.y, 0.f);
            }
            if (OUTH) {
                __half* Cout = (__half*)CoutV;
                *(__half2*)(Cout + m1 * N + n) = __float22half2_rn(v0);
                *(__half2*)(Cout + m2 * N + n) = __float22half2_rn(v1);
            } else {
                float* Cout = (float*)CoutV;
                *(float2*)(Cout + m1 * N + n) = v0;
                *(float2*)(Cout + m2 * N + n) = v1;
            }
        }
    }
}

// ---------------------------------------------------------------------------
// Weight packing (per call; small)
// ---------------------------------------------------------------------------
__global__ void pack_qkvT_kernel(const float* __restrict__ Wq,
                                 const float* __restrict__ Wk,
                                 const float* __restrict__ Wv)
{
    size_t i = (size_t)blockIdx.x * blockDim.x + threadIdx.x;
    const size_t total = (size_t)LL * QKVN * CC;
    if (i >= total) return;
    int k = (int)(i % CC);
    int n = (int)((i / CC) % QKVN);
    int l = (int)(i / ((size_t)CC * QKVN));
    int s = n / CC;
    int h = (n % CC) / DH;
    int d = n % DH;
    const float* W = (s == 0) ? Wq : (s == 1) ? Wk : Wv;
    g_wqkvT[i] = __float2half(W[(((size_t)l * HH + h) * CC + k) * DH + d]);
}

__global__ void transposeW_kernel(const float* __restrict__ W, __half* __restrict__ O,
                                  int Kd, int Nd)
{
    size_t i = (size_t)blockIdx.x * blockDim.x + threadIdx.x;
    size_t total = (size_t)LL * Kd * Nd;
    if (i >= total) return;
    int n = (int)(i % Nd);
    int k = (int)((i / Nd) % Kd);
    int l = (int)(i / ((size_t)Nd * Kd));
    O[((size_t)l * Nd + n) * Kd + k] = __float2half(W[i]);
}

// ---------------------------------------------------------------------------
// Warp LN core: vals = 6 float2 (cols 2*(lane+32*i)), returns mean/rstd
// ---------------------------------------------------------------------------
__device__ __forceinline__ void warp_ln_stats(const float2* v, float& mean, float& rinv)
{
    float s = 0.f, ss = 0.f;
#pragma unroll
    for (int i = 0; i < 6; i++) {
        s  += v[i].x + v[i].y;
        ss += v[i].x * v[i].x + v[i].y * v[i].y;
    }
#pragma unroll
    for (int o = 16; o; o >>= 1) {
        s  += __shfl_xor_sync(0xffffffffu, s,  o);
        ss += __shfl_xor_sync(0xffffffffu, ss, o);
    }
    mean = s * (1.f / CC);
    float var = ss * (1.f / CC) - mean * mean;
    rinv = rsqrtf(var + 1e-5f);
}

// ---------------------------------------------------------------------------
// LayerNorm: warp per row, vectorized; half or float output
// ---------------------------------------------------------------------------
template<bool OUTH>
__global__ void ln_kernel(const float* __restrict__ x,
                          const float* __restrict__ g,
                          const float* __restrict__ b,
                          void* __restrict__ outV)
{
    int row  = blockIdx.x * 8 + (threadIdx.x >> 5);
    int lane = threadIdx.x & 31;
    const float2* xr = (const float2*)(x + (size_t)row * CC);
    const float2* gg = (const float2*)g;
    const float2* bb = (const float2*)b;
    float2 v[6];
#pragma unroll
    for (int i = 0; i < 6; i++) v[i] = xr[lane + 32 * i];
    float mean, rinv;
    warp_ln_stats(v, mean, rinv);
#pragma unroll
    for (int i = 0; i < 6; i++) {
        float2 gv = gg[lane + 32 * i], bv = bb[lane + 32 * i];
        float2 o;
        o.x = (v[i].x - mean) * rinv * gv.x + bv.x;
        o.y = (v[i].y - mean) * rinv * gv.y + bv.y;
        if (OUTH) ((__half2*)outV)[(size_t)row * (CC/2) + lane + 32 * i] = __float22half2_rn(o);
        else      ((float2*)outV)[(size_t)row * (CC/2) + lane + 32 * i] = o;
    }
}

// ---------------------------------------------------------------------------
// Fused embedding + first LayerNorm: writes x (fp32) and ha (half)
// ---------------------------------------------------------------------------
__global__ void embed_ln_kernel(const int* __restrict__ idx,
                                const float* __restrict__ tok,
                                const float* __restrict__ pos,
                                const float* __restrict__ g,
                                const float* __restrict__ b)
{
    int row  = blockIdx.x * 8 + (threadIdx.x >> 5);
    int lane = threadIdx.x & 31;
    int t = row % TT;
    const float2* tr = (const float2*)(tok + (size_t)idx[row] * CC);
    const float2* pr = (const float2*)(pos + (size_t)t * CC);
    const float2* gg = (const float2*)g;
    const float2* bb = (const float2*)b;
    float2 v[6];
    float2* xo = (float2*)(g_x + (size_t)row * CC);
#pragma unroll
    for (int i = 0; i < 6; i++) {
        float2 a = tr[lane + 32 * i], p = pr[lane + 32 * i];
        v[i] = make_float2(a.x + p.x, a.y + p.y);
        xo[lane + 32 * i] = v[i];
    }
    float mean, rinv;
    warp_ln_stats(v, mean, rinv);
    __half2* ho = (__half2*)g_ha + (size_t)row * (CC/2);
#pragma unroll
    for (int i = 0; i < 6; i++) {
        float2 gv = gg[lane + 32 * i], bv = bb[lane + 32 * i];
        float2 o;
        o.x = (v[i].x - mean) * rinv * gv.x + bv.x;
        o.y = (v[i].y - mean) * rinv * gv.y + bv.y;
        ho[lane + 32 * i] = __float22half2_rn(o);
    }
}

// ---------------------------------------------------------------------------
// Attention: one block per (b,h). Kt transposed (conflict-free), register-
// chunked Q in S-phase, float2-vectorized PV. fp32 math, half out.
// ---------------------------------------------------------------------------
__global__ __launch_bounds__(256)
void attn_kernel(const float* __restrict__ qkv, __half* __restrict__ o)
{
    __shared__ float Qs[32][64], Kt[64][33], Vs[32][64], Ss[32][33];

    int bh = blockIdx.x;
    int b  = bh / HH;
    int h  = bh % HH;
    int tid = threadIdx.x;

    // load: 32 rows x 16 float4
    for (int i = tid; i < 32 * 16; i += 256) {
        int t = i >> 4, d4 = i & 15;
        size_t base = (size_t)(b * TT + t) * QKVN + h * DH;
        float4 q = *((const float4*)(qkv + base) + d4);
        float4 k = *((const float4*)(qkv + base + CC) + d4);
        float4 v = *((const float4*)(qkv + base + 2 * CC) + d4);
        ((float4*)Qs[t])[d4] = q;
        ((float4*)Vs[t])[d4] = v;
        int d = d4 * 4;
        Kt[d][t] = k.x; Kt[d + 1][t] = k.y; Kt[d + 2][t] = k.z; Kt[d + 3][t] = k.w;
    }
    __syncthreads();

    // S = Q K^T * scale. warp w handles rows {w, w+8, w+16, w+24}, lane = s.
    // K column cached in regs per 8-d chunk; Q reads are warp-uniform (broadcast).
    {
        int w = tid >> 5, s = tid & 31;
        float acc[4] = {0.f, 0.f, 0.f, 0.f};
        for (int d0 = 0; d0 < 64; d0 += 8) {
            float k[8];
#pragma unroll
            for (int j = 0; j < 8; j++) k[j] = Kt[d0 + j][s];
#pragma unroll
            for (int r = 0; r < 4; r++) {
                int tt = w + 8 * r;
#pragma unroll
                for (int j = 0; j < 8; j++)
                    acc[r] += Qs[tt][d0 + j] * k[j];
            }
        }
#pragma unroll
        for (int r = 0; r < 4; r++)
            Ss[w + 8 * r][s] = acc[r] * 0.125f;   // masked rows handled in softmax
    }
    __syncthreads();

    // softmax: warp per row group (8 warps x 4 rows), lane = s
    {
        int wid = tid >> 5, lane = tid & 31;
#pragma unroll
        for (int r = 0; r < 4; r++) {
            int t = wid * 4 + r;
            float p = (lane <= t) ? Ss[t][lane] : -1e30f;
            float m = p;
#pragma unroll
            for (int off = 16; off; off >>= 1)
                m = fmaxf(m, __shfl_xor_sync(0xffffffffu, m, off));
            float e = (lane <= t) ? __expf(p - m) : 0.f;
            float sum = e;
#pragma unroll
            for (int off = 16; off; off >>= 1)
                sum += __shfl_xor_sync(0xffffffffu, sum, off);
            Ss[t][lane] = e * (1.f / sum);
        }
    }
    __syncthreads();

    // O = P V: warp w rows {w,w+8,w+16,w+24}, lane = d-pair (float2 over 64)
    {
        int w = tid >> 5, lane = tid & 31;
        const float2* Vs2 = (const float2*)&Vs[0][0];   // [32][32] float2
#pragma unroll
        for (int r = 0; r < 4; r++) {
            int tt = w + 8 * r;
            float2 acc = make_float2(0.f, 0.f);
            for (int s = 0; s <= tt; s++) {
                float p = Ss[tt][s];
                float2 v = Vs2[s * 32 + lane];
                acc.x += p * v.x; acc.y += p * v.y;
            }
            *(__half2*)(o + (size_t)(b * TT + tt) * CC + h * DH + 2 * lane) =
                __float22half2_rn(acc);
        }
    }
}

// ---------------------------------------------------------------------------
// LM head: out[n,v] = h[n,:] @ Wlm[:,v] + blm[v]   (V=80, K=384), fp32.
// 320 threads: 8 tokens x 40 lanes, 2 vocab per thread (float2 Wlm loads).
// ---------------------------------------------------------------------------
__global__ __launch_bounds__(320)
void lmhead_kernel(const float* __restrict__ h,
                   const float* __restrict__ Wlm,
                   const float* __restrict__ blm,
                   float* __restrict__ out)
{
    __shared__ float hs[8][CC];
    int tid  = threadIdx.x;
    int row0 = blockIdx.x * 8;
    for (int i = tid; i < 8 * CC; i += 320)
        hs[i / CC][i % CC] = h[(size_t)(row0 + i / CC) * CC + (i % CC)];
    __syncthreads();

    int t = tid / 40;
    int v = (tid % 40) * 2;
    float2 acc = *(const float2*)(blm + v);
#pragma unroll 4
    for (int c = 0; c < CC; c++) {
        float hc = hs[t][c];
        float2 w = *(const float2*)(Wlm + (size_t)c * VV + v);
        acc.x += hc * w.x;
        acc.y += hc * w.y;
    }
    *(float2*)(out + (size_t)(row0 + t) * VV + v) = acc;
}

// ---------------------------------------------------------------------------
// Host launcher
// ---------------------------------------------------------------------------
extern "C" void kernel_launch(void* const* d_in, const int* in_sizes, int n_in,
                              void* d_out, int out_size)
{
    (void)in_sizes; (void)n_in; (void)out_size;
    const int*   idx  = (const int*)  d_in[0];
    const float* tok  = (const float*)d_in[1];
    const float* pos  = (const float*)d_in[2];
    const float* ln1g = (const float*)d_in[3];
    const float* ln1b = (const float*)d_in[4];
    const float* Wq   = (const float*)d_in[5];
    const float* Wk   = (const float*)d_in[6];
    const float* Wv   = (const float*)d_in[7];
    const float* Wo   = (const float*)d_in[8];
    const float* bo   = (const float*)d_in[9];
    const float* ln2g = (const float*)d_in[10];
    const float* ln2b = (const float*)d_in[11];
    const float* W1   = (const float*)d_in[12];
    const float* b1   = (const float*)d_in[13];
    const float* W2   = (const float*)d_in[14];
    const float* b2   = (const float*)d_in[15];
    const float* lnfg = (const float*)d_in[16];
    const float* lnfb = (const float*)d_in[17];
    const float* Wlm  = (const float*)d_in[18];
    const float* blm  = (const float*)d_in[19];
    float* out = (float*)d_out;

    float *px, *pqkv, *phf;
    __half *pha, *po, *phid, *pwqkvT, *pwoT, *pw1T, *pw2T;
    cudaGetSymbolAddress((void**)&px,     g_x);
    cudaGetSymbolAddress((void**)&pqkv,   g_qkv);
    cudaGetSymbolAddress((void**)&phf,    g_hf);
    cudaGetSymbolAddress((void**)&pha,    g_ha);
    cudaGetSymbolAddress((void**)&po,     g_o);
    cudaGetSymbolAddress((void**)&phid,   g_hid);
    cudaGetSymbolAddress((void**)&pwqkvT, g_wqkvT);
    cudaGetSymbolAddress((void**)&pwoT,   g_woT);
    cudaGetSymbolAddress((void**)&pw1T,   g_w1T);
    cudaGetSymbolAddress((void**)&pw2T,   g_w2T);

    cudaFuncSetAttribute(mma_gemm<false, false, false, false>,
                         cudaFuncAttributeMaxDynamicSharedMemorySize, DYN_SMEM);
    cudaFuncSetAttribute(mma_gemm<true, false, true, false>,
                         cudaFuncAttributeMaxDynamicSharedMemorySize, DYN_SMEM);
    cudaFuncSetAttribute(mma_gemm<true, true, false, true>,
                         cudaFuncAttributeMaxDynamicSharedMemorySize, DYN_SMEM);

    // pack half weights
    {
        size_t t1 = (size_t)LL * QKVN * CC;
        pack_qkvT_kernel<<<(int)((t1 + 255) / 256), 256>>>(Wq, Wk, Wv);
        size_t t2 = (size_t)LL * CC * CC;
        transposeW_kernel<<<(int)((t2 + 255) / 256), 256>>>(Wo, pwoT, CC, CC);
        size_t t3 = (size_t)LL * CC * C4;
        transposeW_kernel<<<(int)((t3 + 255) / 256), 256>>>(W1, pw1T, CC, C4);
        size_t t4 = (size_t)LL * C4 * CC;
        transposeW_kernel<<<(int)((t4 + 255) / 256), 256>>>(W2, pw2T, C4, CC);
    }
    // embeddings + ln1 of layer 0 (fused)
    embed_ln_kernel<<<NT / 8, 256>>>(idx, tok, pos, ln1g, ln1b);

    const int MBLK = NT / 128;   // 1024
    for (int l = 0; l < LL; l++) {
        // ln1 -> half (layer 0 already done by embed_ln)
        if (l > 0)
            ln_kernel<true><<<NT / 8, 256>>>(px, ln1g + (size_t)l * CC, ln1b + (size_t)l * CC, pha);
        // qkv = h @ Wqkv   [NT,1152] fp32 out
        mma_gemm<false, false, false, false><<<dim3(QKVN / 128, MBLK), 256, DYN_SMEM>>>(
            pha, pwqkvT + (size_t)l * QKVN * CC, nullptr, nullptr, pqkv, QKVN, CC);
        // attention (fp32 in, half out)
        attn_kernel<<<BB * HH, 256>>>(pqkv, po);
        // x = x + o @ Wo + bo  (fp32 out)
        mma_gemm<true, false, true, false><<<dim3(CC / 128, MBLK), 256, DYN_SMEM>>>(
            po, pwoT + (size_t)l * CC * CC, bo + (size_t)l * CC, px, px, CC, CC);
        // ln2 -> half
        ln_kernel<true><<<NT / 8, 256>>>(px, ln2g + (size_t)l * CC, ln2b + (size_t)l * CC, pha);
        // hid = relu(h @ W1 + b1)   [NT,1536] half out
        mma_gemm<true, true, false, true><<<dim3(C4 / 128, MBLK), 256, DYN_SMEM>>>(
            pha, pw1T + (size_t)l * C4 * CC, b1 + (size_t)l * C4, nullptr, phid, C4, CC);
        // x = x + hid @ W2 + b2  (fp32 out)
        mma_gemm<true, false, true, false><<<dim3(CC / 128, MBLK), 256, DYN_SMEM>>>(
            phid, pw2T + (size_t)l * CC * C4, b2 + (size_t)l * CC, px, px, CC, C4);
    }
    // final LN (fp32) + LM head
    ln_kernel<false><<<NT / 8, 256>>>(px, lnfg, lnfb, phf);
    lmhead_kernel<<<NT / 8, 320>>>(phf, Wlm, blm, out);
}

// round 17
// speedup vs baseline: 1.3404x; 1.0000x over previous
#include <cuda_runtime.h>
#include <cuda_fp16.h>
#include <cstdint>

// Problem constants
#define BB 4096
#define TT 32
#define CC 384
#define HH 6
#define DH 64
#define LL 6
#define VV 80
#define NT (BB*TT)          // 131072 tokens
#define C4 (4*CC)           // 1536
#define QKVN (3*CC)         // 1152

// ---------------------------------------------------------------------------
// Scratch (static device globals; no runtime allocation allowed)
// ---------------------------------------------------------------------------
__device__ float  g_x   [(size_t)NT * CC];      // residual stream (fp32)
__device__ float  g_hf  [(size_t)NT * CC];      // final LN output (fp32)
__device__ __half g_qkvh[(size_t)NT * QKVN];    // q|k|v (half)
__device__ __half g_ha  [(size_t)NT * CC];      // layer LN output (half, GEMM A)
__device__ __half g_o   [(size_t)NT * CC];      // attention output (half)
__device__ __half g_hid [(size_t)NT * C4];      // MLP hidden (half)
// Transposed (K-major, [N][K]) half weights
__device__ __half g_wqkvT[(size_t)LL * QKVN * CC];
__device__ __half g_woT  [(size_t)LL * CC * CC];
__device__ __half g_w1T  [(size_t)LL * C4 * CC];
__device__ __half g_w2T  [(size_t)LL * CC * C4];

// ---------------------------------------------------------------------------
// PTX helpers (sm_80+ baseline — no 'a'-variant instructions)
// ---------------------------------------------------------------------------
__device__ __forceinline__ uint32_t smem_u32(const void* p) {
    return (uint32_t)__cvta_generic_to_shared(p);
}
__device__ __forceinline__ void cp_async16(uint32_t s, const void* g) {
    asm volatile("cp.async.cg.shared.global [%0], [%1], 16;" :: "r"(s), "l"(g));
}
__device__ __forceinline__ void cp_commit() {
    asm volatile("cp.async.commit_group;" ::: "memory");
}
template<int N> __device__ __forceinline__ void cp_wait() {
    asm volatile("cp.async.wait_group %0;" :: "n"(N) : "memory");
}
__device__ __forceinline__ void ldmat_x4(uint32_t* r, uint32_t addr) {
    asm volatile("ldmatrix.sync.aligned.m8n8.x4.shared.b16 {%0,%1,%2,%3}, [%4];"
                 : "=r"(r[0]), "=r"(r[1]), "=r"(r[2]), "=r"(r[3]) : "r"(addr));
}
__device__ __forceinline__ void mma_f16(float* d, const uint32_t* a, uint32_t b0, uint32_t b1) {
    asm volatile(
        "mma.sync.aligned.m16n8k16.row.col.f32.f16.f16.f32 "
        "{%0,%1,%2,%3}, {%4,%5,%6,%7}, {%8,%9}, {%0,%1,%2,%3};"
        : "+f"(d[0]), "+f"(d[1]), "+f"(d[2]), "+f"(d[3])
        : "r"(a[0]), "r"(a[1]), "r"(a[2]), "r"(a[3]), "r"(b0), "r"(b1));
}

// ---------------------------------------------------------------------------
// fp16 ldmatrix GEMM (R11/R8 config — proven best): CTA 128x128, BK=64,
// 3-stage cp.async, 8 warps 2x4. DO NOT TOUCH (at legacy-HMMA rate ceiling).
// ---------------------------------------------------------------------------
#define A_SZ 16384                 // 128 rows * 128B
#define STAGE_BYTES 32768          // A + B
#define NSTG 3
#define DYN_SMEM (NSTG*STAGE_BYTES)  // 98304

#define ISSUE_STAGE(buf, ch) do {                                            \
    uint32_t bA_ = sb + (uint32_t)(buf) * STAGE_BYTES;                       \
    uint32_t bB_ = bA_ + A_SZ;                                               \
    _Pragma("unroll")                                                        \
    for (int i_ = 0; i_ < 4; i_++) {                                         \
        cp_async16(bA_ + offs[i_], gA[i_] + (size_t)(ch) * 64);              \
        cp_async16(bB_ + offs[i_], gB[i_] + (size_t)(ch) * 64);              \
    }                                                                        \
} while (0)

template<bool BIAS, bool RELU, bool RESID, bool OUTH>
__global__ __launch_bounds__(256)
void mma_gemm(const __half* __restrict__ A, const __half* __restrict__ Bt,
              const float* __restrict__ bias, const float* __restrict__ resid,
              void* __restrict__ CoutV, int N, int K)
{
    extern __shared__ char smem[];
    const uint32_t sb = smem_u32(smem);
    const int tid = threadIdx.x;
    const int wid = tid >> 5, lid = tid & 31;
    const int m0 = blockIdx.y * 128;
    const int n0 = blockIdx.x * 128;
    const int wm = (wid & 1) * 64;     // warp M offset
    const int wn = (wid >> 1) * 32;    // warp N offset
    const int g  = lid >> 2;           // groupID
    const int t  = lid & 3;            // thread-in-group

    // cp.async mapping: 1024 16B chunks per (A|B) tile, 4 per thread each.
    uint32_t offs[4];
    const __half* gA[4];
    const __half* gB[4];
#pragma unroll
    for (int i = 0; i < 4; i++) {
        int q   = tid + 256 * i;
        int row = q >> 3;              // 0..127
        int c   = q & 7;               // 16B chunk within 128B row
        offs[i] = (uint32_t)(row * 128 + ((c ^ (row & 7)) << 4));
        gA[i] = A  + (size_t)(m0 + row) * K + c * 8;
        gB[i] = Bt + (size_t)(n0 + row) * K + c * 8;
    }

    // ldmatrix per-lane addressing
    const int lrow = lid & 15;
    const int lsel = lid >> 4;
    const int lx   = lrow & 7;
    const uint32_t aBase = sb + (uint32_t)((wm + lrow) * 128);
    const uint32_t bBase = sb + A_SZ + (uint32_t)((wn + lrow) * 128);

    float acc[4][4][4] = {};
    const int nch = K >> 6;            // K/64

    ISSUE_STAGE(0, 0); cp_commit();
    ISSUE_STAGE(1, 1); cp_commit();

    for (int c = 0; c < nch; ++c) {
        cp_wait<1>();
        __syncthreads();
        int cl = c + 2;
        if (cl < nch) { ISSUE_STAGE(cl % NSTG, cl); }
        cp_commit();

        const uint32_t stg = (uint32_t)((c % NSTG) * STAGE_BYTES);

#pragma unroll
        for (int ks = 0; ks < 4; ++ks) {
            const uint32_t sw = (uint32_t)(((ks * 2 + lsel) ^ lx) << 4);
            uint32_t a[4][4], b[2][4];
#pragma unroll
            for (int mt = 0; mt < 4; mt++)
                ldmat_x4(a[mt], aBase + stg + (uint32_t)(mt * 2048) + sw);
            ldmat_x4(b[0], bBase + stg + sw);
            ldmat_x4(b[1], bBase + stg + 2048u + sw);
#pragma unroll
            for (int mt = 0; mt < 4; mt++)
#pragma unroll
                for (int nt = 0; nt < 4; nt++)
                    mma_f16(acc[mt][nt], a[mt],
                            b[nt >> 1][nt & 1], b[nt >> 1][2 + (nt & 1)]);
        }
    }

    // epilogue
#pragma unroll
    for (int mt = 0; mt < 4; mt++) {
        const size_t m1 = (size_t)m0 + wm + mt * 16 + g;
        const size_t m2 = m1 + 8;
#pragma unroll
        for (int nt = 0; nt < 4; nt++) {
            const int n = n0 + wn + nt * 8 + 2 * t;
            float2 v0 = make_float2(acc[mt][nt][0], acc[mt][nt][1]);
            float2 v1 = make_float2(acc[mt][nt][2], acc[mt][nt][3]);
            if (BIAS) {
                float2 bb = *(const float2*)(bias + n);
                v0.x += bb.x; v0.y += bb.y; v1.x += bb.x; v1.y += bb.y;
            }
            if (RESID) {
                float2 r0 = *(const float2*)(resid + m1 * N + n);
                float2 r1 = *(const float2*)(resid + m2 * N + n);
                v0.x += r0.x; v0.y += r0.y; v1.x += r1.x; v1.y += r1.y;
            }
            if (RELU) {
                v0.x = fmaxf(v0.x, 0.f); v0.y = fmaxf(v0.y, 0.f);
                v1.x = fmaxf(v1.x, 0.f); v1.y = fmaxf(v1.y, 0.f);
            }
            if (OUTH) {
                __half* Cout = (__half*)CoutV;
                *(__half2*)(Cout + m1 * N + n) = __float22half2_rn(v0);
                *(__half2*)(Cout + m2 * N + n) = __float22half2_rn(v1);
            } else {
                float* Cout = (float*)CoutV;
                *(float2*)(Cout + m1 * N + n) = v0;
                *(float2*)(Cout + m2 * N + n) = v1;
            }
        }
    }
}

// ---------------------------------------------------------------------------
// Weight packing (per call; small)
// ---------------------------------------------------------------------------
__global__ void pack_qkvT_kernel(const float* __restrict__ Wq,
                                 const float* __restrict__ Wk,
                                 const float* __restrict__ Wv)
{
    size_t i = (size_t)blockIdx.x * blockDim.x + threadIdx.x;
    const size_t total = (size_t)LL * QKVN * CC;
    if (i >= total) return;
    int k = (int)(i % CC);
    int n = (int)((i / CC) % QKVN);
    int l = (int)(i / ((size_t)CC * QKVN));
    int s = n / CC;
    int h = (n % CC) / DH;
    int d = n % DH;
    const float* W = (s == 0) ? Wq : (s == 1) ? Wk : Wv;
    g_wqkvT[i] = __float2half(W[(((size_t)l * HH + h) * CC + k) * DH + d]);
}

// Tiled transpose: W [L][Kd][Nd] fp32 -> O [L][Nd][Kd] half.
// 32x32 smem tile, coalesced reads AND writes. Block 32x8.
__global__ void transposeW_kernel(const float* __restrict__ W, __half* __restrict__ O,
                                  int Kd, int Nd)
{
    __shared__ __half tile[32][33];
    int l  = blockIdx.z;
    int n0 = blockIdx.x * 32;
    int k0 = blockIdx.y * 32;
    const float* Wl = W + (size_t)l * Kd * Nd;
    __half* Ol = O + (size_t)l * Nd * Kd;
    int tx = threadIdx.x, ty = threadIdx.y;
#pragma unroll
    for (int j = 0; j < 32; j += 8)
        tile[ty + j][tx] = __float2half(Wl[(size_t)(k0 + ty + j) * Nd + n0 + tx]);
    __syncthreads();
#pragma unroll
    for (int j = 0; j < 32; j += 8)
        Ol[(size_t)(n0 + ty + j) * Kd + k0 + tx] = tile[tx][ty + j];
}

// ---------------------------------------------------------------------------
// Warp LN core: vals = 6 float2 (cols 2*(lane+32*i)), returns mean/rstd
// ---------------------------------------------------------------------------
__device__ __forceinline__ void warp_ln_stats(const float2* v, float& mean, float& rinv)
{
    float s = 0.f, ss = 0.f;
#pragma unroll
    for (int i = 0; i < 6; i++) {
        s  += v[i].x + v[i].y;
        ss += v[i].x * v[i].x + v[i].y * v[i].y;
    }
#pragma unroll
    for (int o = 16; o; o >>= 1) {
        s  += __shfl_xor_sync(0xffffffffu, s,  o);
        ss += __shfl_xor_sync(0xffffffffu, ss, o);
    }
    mean = s * (1.f / CC);
    float var = ss * (1.f / CC) - mean * mean;
    rinv = rsqrtf(var + 1e-5f);
}

// ---------------------------------------------------------------------------
// LayerNorm: warp per row, vectorized; half or float output
// ---------------------------------------------------------------------------
template<bool OUTH>
__global__ void ln_kernel(const float* __restrict__ x,
                          const float* __restrict__ g,
                          const float* __restrict__ b,
                          void* __restrict__ outV)
{
    int row  = blockIdx.x * 8 + (threadIdx.x >> 5);
    int lane = threadIdx.x & 31;
    const float2* xr = (const float2*)(x + (size_t)row * CC);
    const float2* gg = (const float2*)g;
    const float2* bb = (const float2*)b;
    float2 v[6];
#pragma unroll
    for (int i = 0; i < 6; i++) v[i] = xr[lane + 32 * i];
    float mean, rinv;
    warp_ln_stats(v, mean, rinv);
#pragma unroll
    for (int i = 0; i < 6; i++) {
        float2 gv = gg[lane + 32 * i], bv = bb[lane + 32 * i];
        float2 o;
        o.x = (v[i].x - mean) * rinv * gv.x + bv.x;
        o.y = (v[i].y - mean) * rinv * gv.y + bv.y;
        if (OUTH) ((__half2*)outV)[(size_t)row * (CC/2) + lane + 32 * i] = __float22half2_rn(o);
        else      ((float2*)outV)[(size_t)row * (CC/2) + lane + 32 * i] = o;
    }
}

// ---------------------------------------------------------------------------
// Fused embedding + first LayerNorm: writes x (fp32) and ha (half)
// ---------------------------------------------------------------------------
__global__ void embed_ln_kernel(const int* __restrict__ idx,
                                const float* __restrict__ tok,
                                const float* __restrict__ pos,
                                const float* __restrict__ g,
                                const float* __restrict__ b)
{
    int row  = blockIdx.x * 8 + (threadIdx.x >> 5);
    int lane = threadIdx.x & 31;
    int t = row % TT;
    const float2* tr = (const float2*)(tok + (size_t)idx[row] * CC);
    const float2* pr = (const float2*)(pos + (size_t)t * CC);
    const float2* gg = (const float2*)g;
    const float2* bb = (const float2*)b;
    float2 v[6];
    float2* xo = (float2*)(g_x + (size_t)row * CC);
#pragma unroll
    for (int i = 0; i < 6; i++) {
        float2 a = tr[lane + 32 * i], p = pr[lane + 32 * i];
        v[i] = make_float2(a.x + p.x, a.y + p.y);
        xo[lane + 32 * i] = v[i];
    }
    float mean, rinv;
    warp_ln_stats(v, mean, rinv);
    __half2* ho = (__half2*)g_ha + (size_t)row * (CC/2);
#pragma unroll
    for (int i = 0; i < 6; i++) {
        float2 gv = gg[lane + 32 * i], bv = bb[lane + 32 * i];
        float2 o;
        o.x = (v[i].x - mean) * rinv * gv.x + bv.x;
        o.y = (v[i].y - mean) * rinv * gv.y + bv.y;
        ho[lane + 32 * i] = __float22half2_rn(o);
    }
}

// ---------------------------------------------------------------------------
// Attention: one block per (b,h). Half QKV in, fp32 smem math, half out.
// Kt transposed (conflict-free), register-chunked Q S-phase, float2 PV.
// ---------------------------------------------------------------------------
__global__ __launch_bounds__(256)
void attn_kernel(const __half* __restrict__ qkv, __half* __restrict__ o)
{
    __shared__ float Qs[32][64], Kt[64][33], Vs[32][64], Ss[32][33];

    int bh = blockIdx.x;
    int b  = bh / HH;
    int h  = bh % HH;
    int tid = threadIdx.x;

    // load: 32 rows x 8 chunks of 8 halves each (uint4)
    for (int i = tid; i < 32 * 8; i += 256) {
        int t = i >> 3, c8 = i & 7;
        size_t base = (size_t)(b * TT + t) * QKVN + h * DH + c8 * 8;
        uint4 rq = *(const uint4*)(qkv + base);
        uint4 rk = *(const uint4*)(qkv + base + CC);
        uint4 rv = *(const uint4*)(qkv + base + 2 * CC);
        const __half2* hq = (const __half2*)&rq;
        const __half2* hk = (const __half2*)&rk;
        const __half2* hv = (const __half2*)&rv;
        int d0 = c8 * 8;
#pragma unroll
        for (int j = 0; j < 4; j++) {
            float2 fq = __half22float2(hq[j]);
            float2 fk = __half22float2(hk[j]);
            float2 fv = __half22float2(hv[j]);
            Qs[t][d0 + 2 * j]     = fq.x;  Qs[t][d0 + 2 * j + 1] = fq.y;
            Vs[t][d0 + 2 * j]     = fv.x;  Vs[t][d0 + 2 * j + 1] = fv.y;
            Kt[d0 + 2 * j][t]     = fk.x;  Kt[d0 + 2 * j + 1][t] = fk.y;
        }
    }
    __syncthreads();

    // S = Q K^T * scale. warp w handles rows {w, w+8, w+16, w+24}, lane = s.
    {
        int w = tid >> 5, s = tid & 31;
        float acc[4] = {0.f, 0.f, 0.f, 0.f};
        for (int d0 = 0; d0 < 64; d0 += 8) {
            float k[8];
#pragma unroll
            for (int j = 0; j < 8; j++) k[j] = Kt[d0 + j][s];
#pragma unroll
            for (int r = 0; r < 4; r++) {
                int tt = w + 8 * r;
#pragma unroll
                for (int j = 0; j < 8; j++)
                    acc[r] += Qs[tt][d0 + j] * k[j];
            }
        }
#pragma unroll
        for (int r = 0; r < 4; r++)
            Ss[w + 8 * r][s] = acc[r] * 0.125f;   // masked rows handled in softmax
    }
    __syncthreads();

    // softmax: warp per row group (8 warps x 4 rows), lane = s
    {
        int wid = tid >> 5, lane = tid & 31;
#pragma unroll
        for (int r = 0; r < 4; r++) {
            int t = wid * 4 + r;
            float p = (lane <= t) ? Ss[t][lane] : -1e30f;
            float m = p;
#pragma unroll
            for (int off = 16; off; off >>= 1)
                m = fmaxf(m, __shfl_xor_sync(0xffffffffu, m, off));
            float e = (lane <= t) ? __expf(p - m) : 0.f;
            float sum = e;
#pragma unroll
            for (int off = 16; off; off >>= 1)
                sum += __shfl_xor_sync(0xffffffffu, sum, off);
            Ss[t][lane] = e * (1.f / sum);
        }
    }
    __syncthreads();

    // O = P V: warp w rows {w,w+8,w+16,w+24}, lane = d-pair (float2 over 64)
    {
        int w = tid >> 5, lane = tid & 31;
        const float2* Vs2 = (const float2*)&Vs[0][0];   // [32][32] float2
#pragma unroll
        for (int r = 0; r < 4; r++) {
            int tt = w + 8 * r;
            float2 acc = make_float2(0.f, 0.f);
            for (int s = 0; s <= tt; s++) {
                float p = Ss[tt][s];
                float2 v = Vs2[s * 32 + lane];
                acc.x += p * v.x; acc.y += p * v.y;
            }
            *(__half2*)(o + (size_t)(b * TT + tt) * CC + h * DH + 2 * lane) =
                __float22half2_rn(acc);
        }
    }
}

// ---------------------------------------------------------------------------
// LM head: out[n,v] = h[n,:] @ Wlm[:,v] + blm[v]   (V=80, K=384), fp32.
// 320 threads: 8 tokens x 40 lanes, 2 vocab per thread (float2 Wlm loads).
// ---------------------------------------------------------------------------
__global__ __launch_bounds__(320)
void lmhead_kernel(const float* __restrict__ h,
                   const float* __restrict__ Wlm,
                   const float* __restrict__ blm,
                   float* __restrict__ out)
{
    __shared__ float hs[8][CC];
    int tid  = threadIdx.x;
    int row0 = blockIdx.x * 8;
    for (int i = tid; i < 8 * CC; i += 320)
        hs[i / CC][i % CC] = h[(size_t)(row0 + i / CC) * CC + (i % CC)];
    __syncthreads();

    int t = tid / 40;
    int v = (tid % 40) * 2;
    float2 acc = *(const float2*)(blm + v);
#pragma unroll 4
    for (int c = 0; c < CC; c++) {
        float hc = hs[t][c];
        float2 w = *(const float2*)(Wlm + (size_t)c * VV + v);
        acc.x += hc * w.x;
        acc.y += hc * w.y;
    }
    *(float2*)(out + (size_t)(row0 + t) * VV + v) = acc;
}

// ---------------------------------------------------------------------------
// Host launcher
// ---------------------------------------------------------------------------
extern "C" void kernel_launch(void* const* d_in, const int* in_sizes, int n_in,
                              void* d_out, int out_size)
{
    (void)in_sizes; (void)n_in; (void)out_size;
    const int*   idx  = (const int*)  d_in[0];
    const float* tok  = (const float*)d_in[1];
    const float* pos  = (const float*)d_in[2];
    const float* ln1g = (const float*)d_in[3];
    const float* ln1b = (const float*)d_in[4];
    const float* Wq   = (const float*)d_in[5];
    const float* Wk   = (const float*)d_in[6];
    const float* Wv   = (const float*)d_in[7];
    const float* Wo   = (const float*)d_in[8];
    const float* bo   = (const float*)d_in[9];
    const float* ln2g = (const float*)d_in[10];
    const float* ln2b = (const float*)d_in[11];
    const float* W1   = (const float*)d_in[12];
    const float* b1   = (const float*)d_in[13];
    const float* W2   = (const float*)d_in[14];
    const float* b2   = (const float*)d_in[15];
    const float* lnfg = (const float*)d_in[16];
    const float* lnfb = (const float*)d_in[17];
    const float* Wlm  = (const float*)d_in[18];
    const float* blm  = (const float*)d_in[19];
    float* out = (float*)d_out;

    float *px, *phf;
    __half *pqkv, *pha, *po, *phid, *pwqkvT, *pwoT, *pw1T, *pw2T;
    cudaGetSymbolAddress((void**)&px,     g_x);
    cudaGetSymbolAddress((void**)&phf,    g_hf);
    cudaGetSymbolAddress((void**)&pqkv,   g_qkvh);
    cudaGetSymbolAddress((void**)&pha,    g_ha);
    cudaGetSymbolAddress((void**)&po,     g_o);
    cudaGetSymbolAddress((void**)&phid,   g_hid);
    cudaGetSymbolAddress((void**)&pwqkvT, g_wqkvT);
    cudaGetSymbolAddress((void**)&pwoT,   g_woT);
    cudaGetSymbolAddress((void**)&pw1T,   g_w1T);
    cudaGetSymbolAddress((void**)&pw2T,   g_w2T);

    cudaFuncSetAttribute(mma_gemm<false, false, false, true>,
                         cudaFuncAttributeMaxDynamicSharedMemorySize, DYN_SMEM);
    cudaFuncSetAttribute(mma_gemm<true, false, true, false>,
                         cudaFuncAttributeMaxDynamicSharedMemorySize, DYN_SMEM);
    cudaFuncSetAttribute(mma_gemm<true, true, false, true>,
                         cudaFuncAttributeMaxDynamicSharedMemorySize, DYN_SMEM);

    // pack half weights (tiled transpose: coalesced reads + writes)
    {
        size_t t1 = (size_t)LL * QKVN * CC;
        pack_qkvT_kernel<<<(int)((t1 + 255) / 256), 256>>>(Wq, Wk, Wv);
        dim3 blk(32, 8);
        transposeW_kernel<<<dim3(CC / 32, CC / 32, LL), blk>>>(Wo, pwoT, CC, CC);
        transposeW_kernel<<<dim3(C4 / 32, CC / 32, LL), blk>>>(W1, pw1T, CC, C4);
        transposeW_kernel<<<dim3(CC / 32, C4 / 32, LL), blk>>>(W2, pw2T, C4, CC);
    }
    // embeddings + ln1 of layer 0 (fused)
    embed_ln_kernel<<<NT / 8, 256>>>(idx, tok, pos, ln1g, ln1b);

    const int MBLK = NT / 128;   // 1024
    for (int l = 0; l < LL; l++) {
        // ln1 -> half (layer 0 already done by embed_ln)
        if (l > 0)
            ln_kernel<true><<<NT / 8, 256>>>(px, ln1g + (size_t)l * CC, ln1b + (size_t)l * CC, pha);
        // qkv = h @ Wqkv   [NT,1152] half out
        mma_gemm<false, false, false, true><<<dim3(QKVN / 128, MBLK), 256, DYN_SMEM>>>(
            pha, pwqkvT + (size_t)l * QKVN * CC, nullptr, nullptr, pqkv, QKVN, CC);
        // attention (half in, half out)
        attn_kernel<<<BB * HH, 256>>>(pqkv, po);
        // x = x + o @ Wo + bo  (fp32 out)
        mma_gemm<true, false, true, false><<<dim3(CC / 128, MBLK), 256, DYN_SMEM>>>(
            po, pwoT + (size_t)l * CC * CC, bo + (size_t)l * CC, px, px, CC, CC);
        // ln2 -> half
        ln_kernel<true><<<NT / 8, 256>>>(px, ln2g + (size_t)l * CC, ln2b + (size_t)l * CC, pha);
        // hid = relu(h @ W1 + b1)   [NT,1536] half out
        mma_gemm<true, true, false, true><<<dim3(C4 / 128, MBLK), 256, DYN_SMEM>>>(
            pha, pw1T + (size_t)l * C4 * CC, b1 + (size_t)l * C4, nullptr, phid, C4, CC);
        // x = x + hid @ W2 + b2  (fp32 out)
        mma_gemm<true, false, true, false><<<dim3(CC / 128, MBLK), 256, DYN_SMEM>>>(
            phid, pw2T + (size_t)l * CC * C4, b2 + (size_t)l * CC, px, px, CC, C4);
    }
    // final LN (fp32) + LM head
    ln_kernel<false><<<NT / 8, 256>>>(px, lnfg, lnfb, phf);
    lmhead_kernel<<<NT / 8, 320>>>(phf, Wlm, blm, out);
}